// round 11
// baseline (speedup 1.0000x reference)
#include <cuda_runtime.h>
#include <cuda_bf16.h>

typedef unsigned long long ull;

// Problem constants
#define BB    8
#define NN    4096
#define WROW  128          // 4096/32 bitmask words per row
#define ROWS  (BB*NN)      // 32768
#define INDIM 16420
#define HID   128
#define NACT  16
#define CK    514          // fc1 split-K chunk (32*514 >= 16420)
#define NQ    16           // column strips per row in agg (256 cols each)

// NATURAL bit layout: word widx, bit b  <->  column widx*32 + b

// ---------------- scratch (static __device__, no allocations) ----------------
__device__ unsigned g_bits[(size_t)ROWS * WROW];   // 16 MB packed adjacency (with self loops)
__device__ float    g_dinv[ROWS];
__device__ float4   g_v [ROWS];                    // dinv * (x @ W1)
__device__ float4   g_v2[ROWS];                    // dinv * (h @ W2)
__device__ float4   g_h2[ROWS];                    // final GCN output h (layer2)
__device__ float4   g_pa[NQ * ROWS];               // layer1 partial sums (col strips)
__device__ float4   g_pb[NQ * ROWS];               // layer2 partial sums
__device__ float    g_zacc[BB * HID];

// ---------------- K1: adj -> bitmask + dinv + v1 + zacc ----------------
// adj values are {0,1} (randint(0,2)), so (adj != 0) == adj. Each lane builds
// whole 32-bit words locally: lane l, chunk k owns word k*32+l, reading 8
// consecutive int4s (128 bytes). Pure LOP3/SHF, no ISETP/VOTE, coalesced STG.
__global__ void __launch_bounds__(256) prep_kernel(
    const int* __restrict__ adj, const float* __restrict__ x,
    const float* __restrict__ W1, const float* __restrict__ fcb1)
{
    int t    = threadIdx.x;
    int warp = (blockIdx.x * 256 + t) >> 5;   // 0..32767 = row
    int lane = t & 31;
    int row  = warp;
    int i    = row & (NN - 1);

    // fused zacc init (block 0 covers all 1024 entries)
    if (blockIdx.x == 0) {
#pragma unroll
        for (int r = 0; r < 4; ++r) {
            int idx = r * 256 + t;
            g_zacc[idx] = fcb1[idx & (HID - 1)];
        }
    }

    const int4* arow = (const int4*)(adj + ((size_t)row << 12));
    unsigned*   brow = g_bits + ((size_t)row << 7);

    int      tw = i >> 5;            // self-loop word
    unsigned tb = 1u << (i & 31);    // self-loop bit

    unsigned cnt = 0;

#pragma unroll
    for (int k = 0; k < 4; ++k) {
        int widx = k * 32 + lane;
        const int4* p = arow + widx * 8;   // cols widx*32 .. widx*32+31
        int4 q0 = __ldcs(p + 0);
        int4 q1 = __ldcs(p + 1);
        int4 q2 = __ldcs(p + 2);
        int4 q3 = __ldcs(p + 3);
        int4 q4 = __ldcs(p + 4);
        int4 q5 = __ldcs(p + 5);
        int4 q6 = __ldcs(p + 6);
        int4 q7 = __ldcs(p + 7);

        unsigned wa = (unsigned)q0.x        | ((unsigned)q0.y << 1)
                    | ((unsigned)q0.z << 2) | ((unsigned)q0.w << 3)
                    | ((unsigned)q1.x << 4) | ((unsigned)q1.y << 5)
                    | ((unsigned)q1.z << 6) | ((unsigned)q1.w << 7);
        unsigned wb = ((unsigned)q2.x << 8)  | ((unsigned)q2.y << 9)
                    | ((unsigned)q2.z << 10) | ((unsigned)q2.w << 11)
                    | ((unsigned)q3.x << 12) | ((unsigned)q3.y << 13)
                    | ((unsigned)q3.z << 14) | ((unsigned)q3.w << 15);
        unsigned wc = ((unsigned)q4.x << 16) | ((unsigned)q4.y << 17)
                    | ((unsigned)q4.z << 18) | ((unsigned)q4.w << 19)
                    | ((unsigned)q5.x << 20) | ((unsigned)q5.y << 21)
                    | ((unsigned)q5.z << 22) | ((unsigned)q5.w << 23);
        unsigned wd = ((unsigned)q6.x << 24) | ((unsigned)q6.y << 25)
                    | ((unsigned)q6.z << 26) | ((unsigned)q6.w << 27)
                    | ((unsigned)q7.x << 28) | ((unsigned)q7.y << 29)
                    | ((unsigned)q7.z << 30) | ((unsigned)q7.w << 31);

        unsigned w = (wa | wb) | (wc | wd);
        if (widx == tw) w |= tb;
        brow[widx] = w;
        cnt += __popc(w);
    }

    // fused degree + dinv + v1
    cnt = __reduce_add_sync(0xffffffffu, cnt);
    if (lane == 0) {
        float d = rsqrtf((float)cnt);
        g_dinv[row] = d;
        float x0 = x[row*3], x1 = x[row*3+1], x2 = x[row*3+2];
        float u0 = x0*W1[0] + x1*W1[3] + x2*W1[6];
        float u1 = x0*W1[1] + x1*W1[4] + x2*W1[7];
        float u2 = x0*W1[2] + x1*W1[5] + x2*W1[8];
        g_v[row] = make_float4(d*u0, d*u1, d*u2, 0.f);
    }
}

// ---------------- quad-LUT aggregation (natural bit order) ----------------
// Strip s covers columns [s*256, s*256+256) = words [s*8, s*8+8).
// Quad (word j in 0..7, nibble k in 0..7) covers cols s*256 + j*32 + k*4 + {0,1,2,3}.

// grid = 2048 blocks: (b in 8) x (rowtile in 16: 256 rows) x (strip in 16)
template<int L>
__global__ void __launch_bounds__(256) agg_kernel()
{
    __shared__ float2 sxy[64 * 16];   // 8 KB
    __shared__ float  szl[64 * 16];   // 4 KB

    const float4* vin  = (L == 0) ? g_v  : g_v2;
    float4*       part = (L == 0) ? g_pa : g_pb;

    int bx = blockIdx.x;
    int b  = bx >> 8;
    int rt = (bx >> 4) & 15;
    int s  = bx & 15;
    int t  = threadIdx.x;

    // ---- build LUTs: thread t -> quad t>>2, entries (t&3)*4 .. +4 ----
    {
        int quad = t >> 2;              // 0..63 = j*8 + k
        int j = quad >> 3, k = quad & 7;
        int base = b * NN + s * 256 + j * 32 + k * 4;
        float4 v0 = vin[base], v1 = vin[base + 1], v2 = vin[base + 2], v3 = vin[base + 3];
        int e0 = (t & 3) * 4;
        float2* exy = &sxy[quad * 16];
        float*  ez  = &szl[quad * 16];
#pragma unroll
        for (int e = 0; e < 4; ++e) {
            int i = e0 + e;
            float sx = 0.f, sy = 0.f, sz = 0.f;
            if (i & 1) { sx += v0.x; sy += v0.y; sz += v0.z; }
            if (i & 2) { sx += v1.x; sy += v1.y; sz += v1.z; }
            if (i & 4) { sx += v2.x; sy += v2.y; sz += v2.z; }
            if (i & 8) { sx += v3.x; sy += v3.y; sz += v3.z; }
            exy[i] = make_float2(sx, sy);
            ez[i]  = sz;
        }
    }
    __syncthreads();

    int row = b * NN + rt * 256 + t;

    const uint4* gw = (const uint4*)(g_bits + (size_t)row * WROW + s * 8);
    uint4 w0 = gw[0], w1 = gw[1];
    unsigned words[8] = { w0.x, w0.y, w0.z, w0.w, w1.x, w1.y, w1.z, w1.w };

    unsigned bxy = (unsigned)__cvta_generic_to_shared(sxy);
    unsigned bz  = (unsigned)__cvta_generic_to_shared(szl);

    ull  accxy0 = 0ull, accxy1 = 0ull;
    float accz0 = 0.f,  accz1 = 0.f;

#pragma unroll
    for (int wl = 0; wl < 8; ++wl) {
        unsigned w = words[wl];
        unsigned rxy = bxy + wl * 1024;   // 8 quads * 128B
        unsigned rz  = bz  + wl * 512;    // 8 quads * 64B
#pragma unroll
        for (int k = 0; k < 8; k += 2) {
            unsigned idx0 = (w >> (4 * k)) & 15u;
            unsigned idx1 = (w >> (4 * k + 4)) & 15u;
            unsigned axy0 = rxy + k * 128 + idx0 * 8;
            unsigned axy1 = rxy + k * 128 + 128 + idx1 * 8;
            unsigned az0  = rz  + k * 64 + idx0 * 4;
            unsigned az1  = rz  + k * 64 + 64 + idx1 * 4;
            ull vxy0, vxy1;
            float vz0, vz1;
            asm volatile("ld.shared.b64 %0, [%1];" : "=l"(vxy0) : "r"(axy0));
            asm volatile("ld.shared.b64 %0, [%1];" : "=l"(vxy1) : "r"(axy1));
            asm volatile("ld.shared.f32 %0, [%1];" : "=f"(vz0) : "r"(az0));
            asm volatile("ld.shared.f32 %0, [%1];" : "=f"(vz1) : "r"(az1));
            asm volatile("add.rn.f32x2 %0, %0, %1;" : "+l"(accxy0) : "l"(vxy0));
            asm volatile("add.rn.f32x2 %0, %0, %1;" : "+l"(accxy1) : "l"(vxy1));
            accz0 += vz0;
            accz1 += vz1;
        }
    }

    ull accxy;
    asm volatile("add.rn.f32x2 %0, %1, %2;" : "=l"(accxy) : "l"(accxy0), "l"(accxy1));
    float ax, ay;
    asm volatile("mov.b64 {%0, %1}, %2;" : "=f"(ax), "=f"(ay) : "l"(accxy));
    part[s * ROWS + row] = make_float4(ax, ay, accz0 + accz1, 0.f);
}

// ---------------- combine layer1 partials, relu, v2 = dinv * (h @ W2) ----------------
__global__ void __launch_bounds__(64) v2_kernel(const float* __restrict__ W2, const float* __restrict__ b1)
{
    int id = blockIdx.x * 64 + threadIdx.x;
    if (id >= ROWS) return;
    float sx = 0.f, sy = 0.f, sz = 0.f;
#pragma unroll
    for (int qq = 0; qq < NQ; ++qq) {
        float4 p = g_pa[qq * ROWS + id];
        sx += p.x; sy += p.y; sz += p.z;
    }
    float d = g_dinv[id];
    float h0 = fmaxf(d * sx + b1[0], 0.f);
    float h1 = fmaxf(d * sy + b1[1], 0.f);
    float h2 = fmaxf(d * sz + b1[2], 0.f);
    float u0 = h0*W2[0] + h1*W2[3] + h2*W2[6];
    float u1 = h0*W2[1] + h1*W2[4] + h2*W2[7];
    float u2 = h0*W2[2] + h1*W2[5] + h2*W2[8];
    g_v2[id] = make_float4(d*u0, d*u1, d*u2, 0.f);
}

// ---------------- combine layer2 partials -> final GCN h ----------------
__global__ void __launch_bounds__(64) combine2_kernel(const float* __restrict__ b2)
{
    int id = blockIdx.x * 64 + threadIdx.x;
    if (id >= ROWS) return;
    float sx = 0.f, sy = 0.f, sz = 0.f;
#pragma unroll
    for (int qq = 0; qq < NQ; ++qq) {
        float4 p = g_pb[qq * ROWS + id];
        sx += p.x; sy += p.y; sz += p.z;
    }
    float d = g_dinv[id];
    g_h2[id] = make_float4(d * sx + b2[0], d * sy + b2[1], d * sz + b2[2], 0.f);
}

// ---------------- fc1 split-K, z built on the fly, atomic accumulate ----------------
__global__ void __launch_bounds__(128) fc1_kernel(
    const float* __restrict__ idxin, const float* __restrict__ y,
    const float* __restrict__ fcW1)
{
    __shared__ float zc[CK];
    int bx = blockIdx.x;
    int b  = bx >> 5;
    int s  = bx & 31;
    int k0 = s * CK;
    int klen = min(CK, INDIM - k0);
    int t = threadIdx.x;

    for (int kk = t; kk < klen; kk += 128) {
        int k = k0 + kk;
        float z;
        if (k < NN) {
            z = idxin[b * NN + k];
        } else if (k < NN + 3 * NN) {
            int g = k - NN;
            int i = g / 3;
            int f = g - i * 3;
            z = ((const float*)&g_h2[b * NN + i])[f];
        } else {
            z = y[b * 36 + (k - (NN + 3 * NN))];
        }
        zc[kk] = z;
    }
    __syncthreads();

    float acc = 0.f;
    const float* wcol = fcW1 + (size_t)k0 * HID + t;
    int kk = 0;
    for (; kk + 4 <= klen; kk += 4) {
        acc += zc[kk+0] * wcol[(size_t)(kk+0) * HID];
        acc += zc[kk+1] * wcol[(size_t)(kk+1) * HID];
        acc += zc[kk+2] * wcol[(size_t)(kk+2) * HID];
        acc += zc[kk+3] * wcol[(size_t)(kk+3) * HID];
    }
    for (; kk < klen; ++kk)
        acc += zc[kk] * wcol[(size_t)kk * HID];

    atomicAdd(&g_zacc[b * HID + t], acc);
}

// ---------------- relu + fc2 ----------------
__global__ void __launch_bounds__(128) fin_kernel(
    const float* __restrict__ fcW2, const float* __restrict__ fcb2, float* __restrict__ out)
{
    __shared__ float sm[HID];
    int b = blockIdx.x, t = threadIdx.x;
    sm[t] = fmaxf(g_zacc[b * HID + t], 0.f);
    __syncthreads();
    if (t < NACT) {
        float o = fcb2[t];
#pragma unroll 8
        for (int h = 0; h < HID; ++h)
            o += sm[h] * fcW2[h * NACT + t];
        out[b * NACT + t] = o;
    }
}

// ---------------- launch ----------------
extern "C" void kernel_launch(void* const* d_in, const int* in_sizes, int n_in,
                              void* d_out, int out_size)
{
    const float* idxin = (const float*)d_in[0];   // [8,4096]
    const float* x     = (const float*)d_in[1];   // [8,4096,3]
    const float* y     = (const float*)d_in[2];   // [8,12,3]
    const int*   adj   = (const int*)  d_in[3];   // [8,4096,4096]
    const float* W1    = (const float*)d_in[4];
    const float* b1    = (const float*)d_in[5];
    const float* W2    = (const float*)d_in[6];
    const float* b2    = (const float*)d_in[7];
    const float* fcW1  = (const float*)d_in[8];
    const float* fcb1  = (const float*)d_in[9];
    const float* fcW2  = (const float*)d_in[10];
    const float* fcb2  = (const float*)d_in[11];
    float* out = (float*)d_out;

    prep_kernel<<<ROWS / 8, 256>>>(adj, x, W1, fcb1);
    agg_kernel<0><<<2048, 256>>>();
    v2_kernel<<<ROWS / 64, 64>>>(W2, b1);
    agg_kernel<1><<<2048, 256>>>();
    combine2_kernel<<<ROWS / 64, 64>>>(b2);
    fc1_kernel<<<BB * 32, 128>>>(idxin, y, fcW1);
    fin_kernel<<<BB, 128>>>(fcW2, fcb2, out);
}

// round 12
// speedup vs baseline: 1.1865x; 1.1865x over previous
#include <cuda_runtime.h>
#include <cuda_bf16.h>

typedef unsigned long long ull;

// Problem constants
#define BB    8
#define NN    4096
#define WROW  128          // 4096/32 bitmask words per row
#define ROWS  (BB*NN)      // 32768
#define INDIM 16420
#define HID   128
#define NACT  16
#define CK    514          // fc1 split-K chunk (32*514 >= 16420)
#define NQ    16           // column strips per row in agg (256 cols each)

// Bit layout (permuted, consistent between prep and agg):
//   word (rd*4 + e), bit l  <->  column rd*128 + l*4 + e     (rd 0..31, e 0..3, l 0..31)

// ---------------- scratch (static __device__, no allocations) ----------------
__device__ unsigned g_bits[(size_t)ROWS * WROW];   // 16 MB packed adjacency (with self loops)
__device__ float    g_dinv[ROWS];
__device__ float4   g_v [ROWS];                    // dinv * (x @ W1)
__device__ float4   g_v2[ROWS];                    // dinv * (h @ W2)
__device__ float4   g_h2[ROWS];                    // final GCN output h (layer2)
__device__ float4   g_pa[NQ * ROWS];               // layer1 partial sums (col strips)
__device__ float4   g_pb[NQ * ROWS];               // layer2 partial sums
__device__ float    g_zacc[BB * HID];
__device__ unsigned g_ctr0[BB * 16];               // agg<0> arrival counters per (b,rt)
__device__ unsigned g_ctr1[BB * 16];               // agg<1> arrival counters
__device__ unsigned g_fcc;                         // fc1 arrival counter

// ---------------- K1: adj -> bitmask + dinv + v1 + zacc + counter reset --------
// Ballot packing (consecutive-lane coalesced loads, 4 lines/LDG), 8-deep pipeline.
// Ballot results are warp-uniform: lane 0 stores uint4 (STG.128), popc uniform.
__global__ void __launch_bounds__(256) prep_kernel(
    const int* __restrict__ adj, const float* __restrict__ x,
    const float* __restrict__ W1, const float* __restrict__ fcb1)
{
    int t    = threadIdx.x;
    int warp = (blockIdx.x * 256 + t) >> 5;   // 0..32767 = row
    int lane = t & 31;
    int row  = warp;
    int i    = row & (NN - 1);

    // fused init (block 0): zacc biases + arrival counters
    if (blockIdx.x == 0) {
#pragma unroll
        for (int r = 0; r < 4; ++r) {
            int idx = r * 256 + t;
            g_zacc[idx] = fcb1[idx & (HID - 1)];
        }
        if (t < BB * 16) { g_ctr0[t] = 0u; g_ctr1[t] = 0u; }
        if (t == 0) g_fcc = 0u;
    }

    const int4* arow = (const int4*)(adj + ((size_t)row << 12));
    unsigned*   brow = g_bits + ((size_t)row << 7);
    uint4*      brow4 = (uint4*)brow;

    // self-loop target: word tw, bit tb (permuted layout)
    int tw = (i >> 7) * 4 + (i & 3);
    unsigned tb = 1u << ((i >> 2) & 31);

    int4 buf[8];
#pragma unroll
    for (int p = 0; p < 8; ++p)
        buf[p] = __ldcs(&arow[p * 32 + lane]);

    unsigned cnt = 0;   // warp-uniform

#pragma unroll 1
    for (int g = 0; g < 4; ++g) {
        int4 cur[8];
#pragma unroll
        for (int p = 0; p < 8; ++p) cur[p] = buf[p];
        if (g < 3) {
#pragma unroll
            for (int p = 0; p < 8; ++p)
                buf[p] = __ldcs(&arow[(g + 1) * 256 + p * 32 + lane]);
        }
#pragma unroll
        for (int p = 0; p < 8; ++p) {
            int rd = g * 8 + p;
            int4 v = cur[p];
            unsigned b0 = __ballot_sync(0xffffffffu, v.x != 0);
            unsigned b1 = __ballot_sync(0xffffffffu, v.y != 0);
            unsigned b2 = __ballot_sync(0xffffffffu, v.z != 0);
            unsigned b3 = __ballot_sync(0xffffffffu, v.w != 0);
            if (lane == 0)
                brow4[rd] = make_uint4(b0, b1, b2, b3);
            cnt += __popc(b0) + __popc(b1) + __popc(b2) + __popc(b3);
        }
    }

    // self-loop post-fix + dinv + v1 (lane 0; cnt is uniform)
    if (lane == 0) {
        unsigned wv = brow[tw];
        cnt += ((wv & tb) == 0u);
        brow[tw] = wv | tb;
        float d = rsqrtf((float)cnt);
        g_dinv[row] = d;
        float x0 = x[row*3], x1 = x[row*3+1], x2 = x[row*3+2];
        float u0 = x0*W1[0] + x1*W1[3] + x2*W1[6];
        float u1 = x0*W1[1] + x1*W1[4] + x2*W1[7];
        float u2 = x0*W1[2] + x1*W1[5] + x2*W1[8];
        g_v[row] = make_float4(d*u0, d*u1, d*u2, 0.f);
    }
}

// ---------------- quad-LUT aggregation core (permuted bit order) ----------------
// Strip s covers columns [s*256, s*256+256) = words [s*8, s*8+8).
// Quad (word j in 0..7, nibble k in 0..7) covers columns:
//   base = s*256 + (j>>2)*128 + k*16 + (j&3),  cols = base + {0,4,8,12}
__device__ __forceinline__ void agg_core(
    const float4* __restrict__ vin, float4* __restrict__ part,
    int b, int rt, int s, int t)
{
    __shared__ float2 sxy[64 * 16];   // 8 KB
    __shared__ float  szl[64 * 16];   // 4 KB

    // ---- build LUTs: thread t -> quad t>>2, entries (t&3)*4 .. +4 ----
    {
        int quad = t >> 2;              // 0..63 = j*8 + k
        int j = quad >> 3, k = quad & 7;
        int base = b * NN + s * 256 + (j >> 2) * 128 + k * 16 + (j & 3);
        float4 v0 = vin[base], v1 = vin[base + 4], v2 = vin[base + 8], v3 = vin[base + 12];
        int e0 = (t & 3) * 4;
        float2* exy = &sxy[quad * 16];
        float*  ez  = &szl[quad * 16];
#pragma unroll
        for (int e = 0; e < 4; ++e) {
            int i = e0 + e;
            float sx = 0.f, sy = 0.f, sz = 0.f;
            if (i & 1) { sx += v0.x; sy += v0.y; sz += v0.z; }
            if (i & 2) { sx += v1.x; sy += v1.y; sz += v1.z; }
            if (i & 4) { sx += v2.x; sy += v2.y; sz += v2.z; }
            if (i & 8) { sx += v3.x; sy += v3.y; sz += v3.z; }
            exy[i] = make_float2(sx, sy);
            ez[i]  = sz;
        }
    }
    __syncthreads();

    int row = b * NN + rt * 256 + t;

    const uint4* gw = (const uint4*)(g_bits + (size_t)row * WROW + s * 8);
    uint4 w0 = gw[0], w1 = gw[1];
    unsigned words[8] = { w0.x, w0.y, w0.z, w0.w, w1.x, w1.y, w1.z, w1.w };

    unsigned bxy = (unsigned)__cvta_generic_to_shared(sxy);
    unsigned bz  = (unsigned)__cvta_generic_to_shared(szl);

    ull  accxy0 = 0ull, accxy1 = 0ull;
    float accz0 = 0.f,  accz1 = 0.f;

#pragma unroll
    for (int wl = 0; wl < 8; ++wl) {
        unsigned w = words[wl];
        unsigned rxy = bxy + wl * 1024;   // 8 quads * 128B
        unsigned rz  = bz  + wl * 512;    // 8 quads * 64B
#pragma unroll
        for (int k = 0; k < 8; k += 2) {
            unsigned idx0 = (w >> (4 * k)) & 15u;
            unsigned idx1 = (w >> (4 * k + 4)) & 15u;
            unsigned axy0 = rxy + k * 128 + idx0 * 8;
            unsigned axy1 = rxy + k * 128 + 128 + idx1 * 8;
            unsigned az0  = rz  + k * 64 + idx0 * 4;
            unsigned az1  = rz  + k * 64 + 64 + idx1 * 4;
            ull vxy0, vxy1;
            float vz0, vz1;
            asm volatile("ld.shared.b64 %0, [%1];" : "=l"(vxy0) : "r"(axy0));
            asm volatile("ld.shared.b64 %0, [%1];" : "=l"(vxy1) : "r"(axy1));
            asm volatile("ld.shared.f32 %0, [%1];" : "=f"(vz0) : "r"(az0));
            asm volatile("ld.shared.f32 %0, [%1];" : "=f"(vz1) : "r"(az1));
            asm volatile("add.rn.f32x2 %0, %0, %1;" : "+l"(accxy0) : "l"(vxy0));
            asm volatile("add.rn.f32x2 %0, %0, %1;" : "+l"(accxy1) : "l"(vxy1));
            accz0 += vz0;
            accz1 += vz1;
        }
    }

    ull accxy;
    asm volatile("add.rn.f32x2 %0, %1, %2;" : "=l"(accxy) : "l"(accxy0), "l"(accxy1));
    float ax, ay;
    asm volatile("mov.b64 {%0, %1}, %2;" : "=f"(ax), "=f"(ay) : "l"(accxy));
    part[s * ROWS + row] = make_float4(ax, ay, accz0 + accz1, 0.f);
}

// ---------------- agg layer 1 + fused v2 epilogue (last-arriving block) --------
__global__ void __launch_bounds__(256) agg1_kernel(
    const float* __restrict__ W2, const float* __restrict__ b1)
{
    int bx = blockIdx.x;
    int b  = bx >> 8;
    int rt = (bx >> 4) & 15;
    int s  = bx & 15;
    int t  = threadIdx.x;

    agg_core(g_v, g_pa, b, rt, s, t);

    // arrival + epilogue: last of the 16 strip-blocks for (b,rt) computes v2
    __shared__ unsigned s_last;
    __threadfence();
    __syncthreads();
    if (t == 0) s_last = atomicAdd(&g_ctr0[b * 16 + rt], 1u);
    __syncthreads();
    if (s_last == 15u) {
        __threadfence();
        int id = b * NN + rt * 256 + t;
        float sx = 0.f, sy = 0.f, sz = 0.f;
#pragma unroll
        for (int qq = 0; qq < NQ; ++qq) {
            float4 p = __ldcg(&g_pa[qq * ROWS + id]);
            sx += p.x; sy += p.y; sz += p.z;
        }
        float d = g_dinv[id];
        float h0 = fmaxf(d * sx + b1[0], 0.f);
        float h1 = fmaxf(d * sy + b1[1], 0.f);
        float h2 = fmaxf(d * sz + b1[2], 0.f);
        float u0 = h0*W2[0] + h1*W2[3] + h2*W2[6];
        float u1 = h0*W2[1] + h1*W2[4] + h2*W2[7];
        float u2 = h0*W2[2] + h1*W2[5] + h2*W2[8];
        g_v2[id] = make_float4(d*u0, d*u1, d*u2, 0.f);
    }
}

// ---------------- agg layer 2 + fused combine2 epilogue ----------------
__global__ void __launch_bounds__(256) agg2_kernel(const float* __restrict__ b2)
{
    int bx = blockIdx.x;
    int b  = bx >> 8;
    int rt = (bx >> 4) & 15;
    int s  = bx & 15;
    int t  = threadIdx.x;

    agg_core(g_v2, g_pb, b, rt, s, t);

    __shared__ unsigned s_last;
    __threadfence();
    __syncthreads();
    if (t == 0) s_last = atomicAdd(&g_ctr1[b * 16 + rt], 1u);
    __syncthreads();
    if (s_last == 15u) {
        __threadfence();
        int id = b * NN + rt * 256 + t;
        float sx = 0.f, sy = 0.f, sz = 0.f;
#pragma unroll
        for (int qq = 0; qq < NQ; ++qq) {
            float4 p = __ldcg(&g_pb[qq * ROWS + id]);
            sx += p.x; sy += p.y; sz += p.z;
        }
        float d = g_dinv[id];
        g_h2[id] = make_float4(d * sx + b2[0], d * sy + b2[1], d * sz + b2[2], 0.f);
    }
}

// ---------------- fc1 split-K + fused fin epilogue ----------------
__global__ void __launch_bounds__(128) fc1_kernel(
    const float* __restrict__ idxin, const float* __restrict__ y,
    const float* __restrict__ fcW1, const float* __restrict__ fcW2,
    const float* __restrict__ fcb2, float* __restrict__ out)
{
    __shared__ float zc[CK];
    int bx = blockIdx.x;
    int b  = bx >> 5;
    int s  = bx & 31;
    int k0 = s * CK;
    int klen = min(CK, INDIM - k0);
    int t = threadIdx.x;

    for (int kk = t; kk < klen; kk += 128) {
        int k = k0 + kk;
        float z;
        if (k < NN) {
            z = idxin[b * NN + k];
        } else if (k < NN + 3 * NN) {
            int g = k - NN;
            int i = g / 3;
            int f = g - i * 3;
            z = ((const float*)&g_h2[b * NN + i])[f];
        } else {
            z = y[b * 36 + (k - (NN + 3 * NN))];
        }
        zc[kk] = z;
    }
    __syncthreads();

    float acc = 0.f;
    const float* wcol = fcW1 + (size_t)k0 * HID + t;
    int kk = 0;
    for (; kk + 4 <= klen; kk += 4) {
        acc += zc[kk+0] * wcol[(size_t)(kk+0) * HID];
        acc += zc[kk+1] * wcol[(size_t)(kk+1) * HID];
        acc += zc[kk+2] * wcol[(size_t)(kk+2) * HID];
        acc += zc[kk+3] * wcol[(size_t)(kk+3) * HID];
    }
    for (; kk < klen; ++kk)
        acc += zc[kk] * wcol[(size_t)kk * HID];

    atomicAdd(&g_zacc[b * HID + t], acc);

    // last of the 256 blocks computes the whole fc2 output (128 = 8 batches x 16 acts)
    __shared__ unsigned s_last;
    __threadfence();
    __syncthreads();
    if (t == 0) s_last = atomicAdd(&g_fcc, 1u);
    __syncthreads();
    if (s_last == 255u) {
        __threadfence();
        int ob = t >> 4;          // batch
        int oa = t & 15;          // action
        float o = fcb2[oa];
#pragma unroll 8
        for (int h = 0; h < HID; ++h)
            o += fmaxf(__ldcg(&g_zacc[ob * HID + h]), 0.f) * fcW2[h * NACT + oa];
        out[ob * NACT + oa] = o;
    }
}

// ---------------- launch ----------------
extern "C" void kernel_launch(void* const* d_in, const int* in_sizes, int n_in,
                              void* d_out, int out_size)
{
    const float* idxin = (const float*)d_in[0];   // [8,4096]
    const float* x     = (const float*)d_in[1];   // [8,4096,3]
    const float* y     = (const float*)d_in[2];   // [8,12,3]
    const int*   adj   = (const int*)  d_in[3];   // [8,4096,4096]
    const float* W1    = (const float*)d_in[4];
    const float* b1    = (const float*)d_in[5];
    const float* W2    = (const float*)d_in[6];
    const float* b2    = (const float*)d_in[7];
    const float* fcW1  = (const float*)d_in[8];
    const float* fcb1  = (const float*)d_in[9];
    const float* fcW2  = (const float*)d_in[10];
    const float* fcb2  = (const float*)d_in[11];
    float* out = (float*)d_out;

    prep_kernel<<<ROWS / 8, 256>>>(adj, x, W1, fcb1);
    agg1_kernel<<<2048, 256>>>(W2, b1);
    agg2_kernel<<<2048, 256>>>(b2);
    fc1_kernel<<<BB * 32, 128>>>(idxin, y, fcW1, fcW2, fcb2, out);
}

// round 13
// speedup vs baseline: 1.3118x; 1.1056x over previous
#include <cuda_runtime.h>
#include <cuda_bf16.h>

typedef unsigned long long ull;

// Problem constants
#define BB    8
#define NN    4096
#define WROW  128          // 4096/32 bitmask words per row
#define ROWS  (BB*NN)      // 32768
#define INDIM 16420
#define HID   128
#define NACT  16
#define FCSPLIT 128        // fc1 split-K chunks per batch
#define CK    129          // fc1 split-K chunk size (128*129 >= 16420)
#define NQ    16           // column strips per row in agg (256 cols each)

// Bit layout (permuted, consistent between prep and agg):
//   word (rd*4 + e), bit l  <->  column rd*128 + l*4 + e     (rd 0..31, e 0..3, l 0..31)

// ---------------- scratch (static __device__, no allocations) ----------------
__device__ unsigned g_bits[(size_t)ROWS * WROW];   // 16 MB packed adjacency (with self loops)
__device__ float    g_dinv[ROWS];
__device__ float4   g_v [ROWS];                    // dinv * (x @ W1)
__device__ float4   g_v2[ROWS];                    // dinv * (h @ W2)
__device__ float4   g_h2[ROWS];                    // final GCN output h (layer2)
__device__ float4   g_pa[NQ * ROWS];               // layer1 partial sums (col strips)
__device__ float4   g_pb[NQ * ROWS];               // layer2 partial sums
__device__ float    g_zacc[BB * HID];
__device__ unsigned g_ctr0[BB * 16];               // agg1 arrival counters per (b,rt)
__device__ unsigned g_ctr1[BB * 16];               // agg2 arrival counters
__device__ unsigned g_fcc;                         // fc1 arrival counter

// ---------------- K1: adj -> bitmask + dinv + v1 + zacc + counter reset --------
__global__ void __launch_bounds__(256) prep_kernel(
    const int* __restrict__ adj, const float* __restrict__ x,
    const float* __restrict__ W1, const float* __restrict__ fcb1)
{
    int t    = threadIdx.x;
    int warp = (blockIdx.x * 256 + t) >> 5;   // 0..32767 = row
    int lane = t & 31;
    int row  = warp;
    int i    = row & (NN - 1);

    // fused init (block 0): zacc biases + arrival counters
    if (blockIdx.x == 0) {
#pragma unroll
        for (int r = 0; r < 4; ++r) {
            int idx = r * 256 + t;
            g_zacc[idx] = fcb1[idx & (HID - 1)];
        }
        if (t < BB * 16) { g_ctr0[t] = 0u; g_ctr1[t] = 0u; }
        if (t == 0) g_fcc = 0u;
    }

    const int4* arow = (const int4*)(adj + ((size_t)row << 12));
    unsigned*   brow = g_bits + ((size_t)row << 7);
    uint4*      brow4 = (uint4*)brow;

    // self-loop target: word tw, bit tb (permuted layout)
    int tw = (i >> 7) * 4 + (i & 3);
    unsigned tb = 1u << ((i >> 2) & 31);

    int4 buf[8];
#pragma unroll
    for (int p = 0; p < 8; ++p)
        buf[p] = __ldcs(&arow[p * 32 + lane]);

    unsigned cnt = 0;   // warp-uniform

#pragma unroll 1
    for (int g = 0; g < 4; ++g) {
        int4 cur[8];
#pragma unroll
        for (int p = 0; p < 8; ++p) cur[p] = buf[p];
        if (g < 3) {
#pragma unroll
            for (int p = 0; p < 8; ++p)
                buf[p] = __ldcs(&arow[(g + 1) * 256 + p * 32 + lane]);
        }
#pragma unroll
        for (int p = 0; p < 8; ++p) {
            int rd = g * 8 + p;
            int4 v = cur[p];
            unsigned b0 = __ballot_sync(0xffffffffu, v.x != 0);
            unsigned b1 = __ballot_sync(0xffffffffu, v.y != 0);
            unsigned b2 = __ballot_sync(0xffffffffu, v.z != 0);
            unsigned b3 = __ballot_sync(0xffffffffu, v.w != 0);
            if (lane == 0)
                brow4[rd] = make_uint4(b0, b1, b2, b3);
            cnt += __popc(b0) + __popc(b1) + __popc(b2) + __popc(b3);
        }
    }

    // self-loop post-fix + dinv + v1 (lane 0; cnt is uniform)
    if (lane == 0) {
        unsigned wv = brow[tw];
        cnt += ((wv & tb) == 0u);
        brow[tw] = wv | tb;
        float d = rsqrtf((float)cnt);
        g_dinv[row] = d;
        float x0 = x[row*3], x1 = x[row*3+1], x2 = x[row*3+2];
        float u0 = x0*W1[0] + x1*W1[3] + x2*W1[6];
        float u1 = x0*W1[1] + x1*W1[4] + x2*W1[7];
        float u2 = x0*W1[2] + x1*W1[5] + x2*W1[8];
        g_v[row] = make_float4(d*u0, d*u1, d*u2, 0.f);
    }
}

// ---------------- quad-LUT aggregation core (permuted bit order) ----------------
__device__ __forceinline__ void agg_core(
    const float4* __restrict__ vin, float4* __restrict__ part,
    int b, int rt, int s, int t)
{
    __shared__ float2 sxy[64 * 16];   // 8 KB
    __shared__ float  szl[64 * 16];   // 4 KB

    // ---- build LUTs: thread t -> quad t>>2, entries (t&3)*4 .. +4 ----
    {
        int quad = t >> 2;              // 0..63 = j*8 + k
        int j = quad >> 3, k = quad & 7;
        int base = b * NN + s * 256 + (j >> 2) * 128 + k * 16 + (j & 3);
        float4 v0 = vin[base], v1 = vin[base + 4], v2 = vin[base + 8], v3 = vin[base + 12];
        int e0 = (t & 3) * 4;
        float2* exy = &sxy[quad * 16];
        float*  ez  = &szl[quad * 16];
#pragma unroll
        for (int e = 0; e < 4; ++e) {
            int i = e0 + e;
            float sx = 0.f, sy = 0.f, sz = 0.f;
            if (i & 1) { sx += v0.x; sy += v0.y; sz += v0.z; }
            if (i & 2) { sx += v1.x; sy += v1.y; sz += v1.z; }
            if (i & 4) { sx += v2.x; sy += v2.y; sz += v2.z; }
            if (i & 8) { sx += v3.x; sy += v3.y; sz += v3.z; }
            exy[i] = make_float2(sx, sy);
            ez[i]  = sz;
        }
    }
    __syncthreads();

    int row = b * NN + rt * 256 + t;

    const uint4* gw = (const uint4*)(g_bits + (size_t)row * WROW + s * 8);
    uint4 w0 = gw[0], w1 = gw[1];
    unsigned words[8] = { w0.x, w0.y, w0.z, w0.w, w1.x, w1.y, w1.z, w1.w };

    unsigned bxy = (unsigned)__cvta_generic_to_shared(sxy);
    unsigned bz  = (unsigned)__cvta_generic_to_shared(szl);

    ull  accxy0 = 0ull, accxy1 = 0ull;
    float accz0 = 0.f,  accz1 = 0.f;

#pragma unroll
    for (int wl = 0; wl < 8; ++wl) {
        unsigned w = words[wl];
        unsigned rxy = bxy + wl * 1024;   // 8 quads * 128B
        unsigned rz  = bz  + wl * 512;    // 8 quads * 64B
#pragma unroll
        for (int k = 0; k < 8; k += 2) {
            unsigned idx0 = (w >> (4 * k)) & 15u;
            unsigned idx1 = (w >> (4 * k + 4)) & 15u;
            unsigned axy0 = rxy + k * 128 + idx0 * 8;
            unsigned axy1 = rxy + k * 128 + 128 + idx1 * 8;
            unsigned az0  = rz  + k * 64 + idx0 * 4;
            unsigned az1  = rz  + k * 64 + 64 + idx1 * 4;
            ull vxy0, vxy1;
            float vz0, vz1;
            asm volatile("ld.shared.b64 %0, [%1];" : "=l"(vxy0) : "r"(axy0));
            asm volatile("ld.shared.b64 %0, [%1];" : "=l"(vxy1) : "r"(axy1));
            asm volatile("ld.shared.f32 %0, [%1];" : "=f"(vz0) : "r"(az0));
            asm volatile("ld.shared.f32 %0, [%1];" : "=f"(vz1) : "r"(az1));
            asm volatile("add.rn.f32x2 %0, %0, %1;" : "+l"(accxy0) : "l"(vxy0));
            asm volatile("add.rn.f32x2 %0, %0, %1;" : "+l"(accxy1) : "l"(vxy1));
            accz0 += vz0;
            accz1 += vz1;
        }
    }

    ull accxy;
    asm volatile("add.rn.f32x2 %0, %1, %2;" : "=l"(accxy) : "l"(accxy0), "l"(accxy1));
    float ax, ay;
    asm volatile("mov.b64 {%0, %1}, %2;" : "=f"(ax), "=f"(ay) : "l"(accxy));
    part[s * ROWS + row] = make_float4(ax, ay, accz0 + accz1, 0.f);
}

// ---------------- agg layer 1 + fused v2 epilogue (last-arriving block) --------
__global__ void __launch_bounds__(256) agg1_kernel(
    const float* __restrict__ W2, const float* __restrict__ b1)
{
    int bx = blockIdx.x;
    int b  = bx >> 8;
    int rt = (bx >> 4) & 15;
    int s  = bx & 15;
    int t  = threadIdx.x;

    agg_core(g_v, g_pa, b, rt, s, t);

    __shared__ unsigned s_last;
    __threadfence();
    __syncthreads();
    if (t == 0) s_last = atomicAdd(&g_ctr0[b * 16 + rt], 1u);
    __syncthreads();
    if (s_last == 15u) {
        __threadfence();
        int id = b * NN + rt * 256 + t;
        float sx = 0.f, sy = 0.f, sz = 0.f;
#pragma unroll
        for (int qq = 0; qq < NQ; ++qq) {
            float4 p = __ldcg(&g_pa[qq * ROWS + id]);
            sx += p.x; sy += p.y; sz += p.z;
        }
        float d = g_dinv[id];
        float h0 = fmaxf(d * sx + b1[0], 0.f);
        float h1 = fmaxf(d * sy + b1[1], 0.f);
        float h2 = fmaxf(d * sz + b1[2], 0.f);
        float u0 = h0*W2[0] + h1*W2[3] + h2*W2[6];
        float u1 = h0*W2[1] + h1*W2[4] + h2*W2[7];
        float u2 = h0*W2[2] + h1*W2[5] + h2*W2[8];
        g_v2[id] = make_float4(d*u0, d*u1, d*u2, 0.f);
    }
}

// ---------------- agg layer 2 + fused combine2 epilogue ----------------
__global__ void __launch_bounds__(256) agg2_kernel(const float* __restrict__ b2)
{
    int bx = blockIdx.x;
    int b  = bx >> 8;
    int rt = (bx >> 4) & 15;
    int s  = bx & 15;
    int t  = threadIdx.x;

    agg_core(g_v2, g_pb, b, rt, s, t);

    __shared__ unsigned s_last;
    __threadfence();
    __syncthreads();
    if (t == 0) s_last = atomicAdd(&g_ctr1[b * 16 + rt], 1u);
    __syncthreads();
    if (s_last == 15u) {
        __threadfence();
        int id = b * NN + rt * 256 + t;
        float sx = 0.f, sy = 0.f, sz = 0.f;
#pragma unroll
        for (int qq = 0; qq < NQ; ++qq) {
            float4 p = __ldcg(&g_pb[qq * ROWS + id]);
            sx += p.x; sy += p.y; sz += p.z;
        }
        float d = g_dinv[id];
        g_h2[id] = make_float4(d * sx + b2[0], d * sy + b2[1], d * sz + b2[2], 0.f);
    }
}

// ---------------- fc1 split-K (128 chunks/batch) + fused fin epilogue ----------
__global__ void __launch_bounds__(128) fc1_kernel(
    const float* __restrict__ idxin, const float* __restrict__ y,
    const float* __restrict__ fcW1, const float* __restrict__ fcW2,
    const float* __restrict__ fcb2, float* __restrict__ out)
{
    __shared__ float zc[CK];
    int bx = blockIdx.x;
    int b  = bx >> 7;            // batch
    int s  = bx & 127;           // split
    int k0 = s * CK;
    int klen = min(CK, INDIM - k0);
    int t = threadIdx.x;

    for (int kk = t; kk < klen; kk += 128) {
        int k = k0 + kk;
        float z;
        if (k < NN) {
            z = idxin[b * NN + k];
        } else if (k < NN + 3 * NN) {
            int g = k - NN;
            int i = g / 3;
            int f = g - i * 3;
            z = ((const float*)&g_h2[b * NN + i])[f];
        } else {
            z = y[b * 36 + (k - (NN + 3 * NN))];
        }
        zc[kk] = z;
    }
    __syncthreads();

    float acc = 0.f;
    const float* wcol = fcW1 + (size_t)k0 * HID + t;
    int kk = 0;
    for (; kk + 8 <= klen; kk += 8) {
        acc += zc[kk+0] * wcol[(size_t)(kk+0) * HID];
        acc += zc[kk+1] * wcol[(size_t)(kk+1) * HID];
        acc += zc[kk+2] * wcol[(size_t)(kk+2) * HID];
        acc += zc[kk+3] * wcol[(size_t)(kk+3) * HID];
        acc += zc[kk+4] * wcol[(size_t)(kk+4) * HID];
        acc += zc[kk+5] * wcol[(size_t)(kk+5) * HID];
        acc += zc[kk+6] * wcol[(size_t)(kk+6) * HID];
        acc += zc[kk+7] * wcol[(size_t)(kk+7) * HID];
    }
    for (; kk < klen; ++kk)
        acc += zc[kk] * wcol[(size_t)kk * HID];

    atomicAdd(&g_zacc[b * HID + t], acc);

    // last of the BB*FCSPLIT blocks computes fc2 (128 = 8 batches x 16 actions)
    __shared__ unsigned s_last;
    __threadfence();
    __syncthreads();
    if (t == 0) s_last = atomicAdd(&g_fcc, 1u);
    __syncthreads();
    if (s_last == (unsigned)(BB * FCSPLIT - 1)) {
        __threadfence();
        int ob = t >> 4;          // batch
        int oa = t & 15;          // action
        float o = fcb2[oa];
#pragma unroll 8
        for (int h = 0; h < HID; ++h)
            o += fmaxf(__ldcg(&g_zacc[ob * HID + h]), 0.f) * fcW2[h * NACT + oa];
        out[ob * NACT + oa] = o;
    }
}

// ---------------- launch ----------------
extern "C" void kernel_launch(void* const* d_in, const int* in_sizes, int n_in,
                              void* d_out, int out_size)
{
    const float* idxin = (const float*)d_in[0];   // [8,4096]
    const float* x     = (const float*)d_in[1];   // [8,4096,3]
    const float* y     = (const float*)d_in[2];   // [8,12,3]
    const int*   adj   = (const int*)  d_in[3];   // [8,4096,4096]
    const float* W1    = (const float*)d_in[4];
    const float* b1    = (const float*)d_in[5];
    const float* W2    = (const float*)d_in[6];
    const float* b2    = (const float*)d_in[7];
    const float* fcW1  = (const float*)d_in[8];
    const float* fcb1  = (const float*)d_in[9];
    const float* fcW2  = (const float*)d_in[10];
    const float* fcb2  = (const float*)d_in[11];
    float* out = (float*)d_out;

    prep_kernel<<<ROWS / 8, 256>>>(adj, x, W1, fcb1);
    agg1_kernel<<<2048, 256>>>(W2, b1);
    agg2_kernel<<<2048, 256>>>(b2);
    fc1_kernel<<<BB * FCSPLIT, 128>>>(idxin, y, fcW1, fcW2, fcb2, out);
}

// round 15
// speedup vs baseline: 1.3175x; 1.0043x over previous
#include <cuda_runtime.h>
#include <cuda_bf16.h>

typedef unsigned long long ull;

// Problem constants
#define BB    8
#define NN    4096
#define WROW  128          // 4096/32 bitmask words per row
#define ROWS  (BB*NN)      // 32768
#define INDIM 16420
#define HID   128
#define NACT  16
#define FCSPLIT 128        // fc1 split-K chunks per batch
#define CK    129          // fc1 split-K chunk size (128*129 >= 16420)
#define NQ    16           // column strips per row in agg (256 cols each)

// Bit layout (permuted, consistent between prep and agg):
//   word (rd*4 + e), bit l  <->  column rd*128 + l*4 + e     (rd 0..31, e 0..3, l 0..31)

// ---------------- scratch (static __device__, no allocations) ----------------
__device__ unsigned g_bits[(size_t)ROWS * WROW];   // 16 MB packed adjacency (with self loops)
__device__ float    g_dinv[ROWS];
__device__ float4   g_v [ROWS];                    // dinv * (x @ W1)
__device__ float4   g_v2[ROWS];                    // dinv * (h @ W2)
__device__ float4   g_h2[ROWS];                    // final GCN output h (layer2)
__device__ float4   g_pa[NQ * ROWS];               // layer1 partial sums (col strips)
__device__ float4   g_pb[NQ * ROWS];               // layer2 partial sums
__device__ float    g_zacc[BB * HID];
__device__ unsigned g_ctr0[BB * 16];               // agg1 arrival counters per (b,rt)
__device__ unsigned g_ctr1[BB * 16];               // agg2 arrival counters
__device__ unsigned g_fcc;                         // fc1 arrival counter

// ---------------- K1: adj -> bitmask + dinv + v1 + zacc + counter reset --------
__global__ void __launch_bounds__(256) prep_kernel(
    const int* __restrict__ adj, const float* __restrict__ x,
    const float* __restrict__ W1, const float* __restrict__ fcb1)
{
    int t    = threadIdx.x;
    int warp = (blockIdx.x * 256 + t) >> 5;   // 0..32767 = row
    int lane = t & 31;
    int row  = warp;
    int i    = row & (NN - 1);

    // fused init (block 0): zacc biases + arrival counters
    if (blockIdx.x == 0) {
#pragma unroll
        for (int r = 0; r < 4; ++r) {
            int idx = r * 256 + t;
            g_zacc[idx] = fcb1[idx & (HID - 1)];
        }
        if (t < BB * 16) { g_ctr0[t] = 0u; g_ctr1[t] = 0u; }
        if (t == 0) g_fcc = 0u;
    }

    const int4* arow = (const int4*)(adj + ((size_t)row << 12));
    unsigned*   brow = g_bits + ((size_t)row << 7);
    uint4*      brow4 = (uint4*)brow;

    // self-loop target: word tw, bit tb (permuted layout)
    int tw = (i >> 7) * 4 + (i & 3);
    unsigned tb = 1u << ((i >> 2) & 31);

    int4 buf[8];
#pragma unroll
    for (int p = 0; p < 8; ++p)
        buf[p] = __ldcs(&arow[p * 32 + lane]);

    unsigned cnt = 0;   // warp-uniform

#pragma unroll 1
    for (int g = 0; g < 4; ++g) {
        int4 cur[8];
#pragma unroll
        for (int p = 0; p < 8; ++p) cur[p] = buf[p];
        if (g < 3) {
#pragma unroll
            for (int p = 0; p < 8; ++p)
                buf[p] = __ldcs(&arow[(g + 1) * 256 + p * 32 + lane]);
        }
#pragma unroll
        for (int p = 0; p < 8; ++p) {
            int rd = g * 8 + p;
            int4 v = cur[p];
            unsigned b0 = __ballot_sync(0xffffffffu, v.x != 0);
            unsigned b1 = __ballot_sync(0xffffffffu, v.y != 0);
            unsigned b2 = __ballot_sync(0xffffffffu, v.z != 0);
            unsigned b3 = __ballot_sync(0xffffffffu, v.w != 0);
            if (lane == 0)
                brow4[rd] = make_uint4(b0, b1, b2, b3);
            cnt += __popc(b0) + __popc(b1) + __popc(b2) + __popc(b3);
        }
    }

    // self-loop post-fix + dinv + v1 (lane 0; cnt is uniform)
    if (lane == 0) {
        unsigned wv = brow[tw];
        cnt += ((wv & tb) == 0u);
        brow[tw] = wv | tb;
        float d = rsqrtf((float)cnt);
        g_dinv[row] = d;
        float x0 = x[row*3], x1 = x[row*3+1], x2 = x[row*3+2];
        float u0 = x0*W1[0] + x1*W1[3] + x2*W1[6];
        float u1 = x0*W1[1] + x1*W1[4] + x2*W1[7];
        float u2 = x0*W1[2] + x1*W1[5] + x2*W1[8];
        g_v[row] = make_float4(d*u0, d*u1, d*u2, 0.f);
    }
}

// ---------------- quad-LUT aggregation core (permuted bit order) ----------------
__device__ __forceinline__ void agg_core(
    const float4* __restrict__ vin, float4* __restrict__ part,
    int b, int rt, int s, int t)
{
    __shared__ float2 sxy[64 * 16];   // 8 KB
    __shared__ float  szl[64 * 16];   // 4 KB

    // ---- build LUTs: thread t -> quad t>>2, entries (t&3)*4 .. +4 ----
    {
        int quad = t >> 2;              // 0..63 = j*8 + k
        int j = quad >> 3, k = quad & 7;
        int base = b * NN + s * 256 + (j >> 2) * 128 + k * 16 + (j & 3);
        float4 v0 = vin[base], v1 = vin[base + 4], v2 = vin[base + 8], v3 = vin[base + 12];
        int e0 = (t & 3) * 4;
        float2* exy = &sxy[quad * 16];
        float*  ez  = &szl[quad * 16];
#pragma unroll
        for (int e = 0; e < 4; ++e) {
            int i = e0 + e;
            float sx = 0.f, sy = 0.f, sz = 0.f;
            if (i & 1) { sx += v0.x; sy += v0.y; sz += v0.z; }
            if (i & 2) { sx += v1.x; sy += v1.y; sz += v1.z; }
            if (i & 4) { sx += v2.x; sy += v2.y; sz += v2.z; }
            if (i & 8) { sx += v3.x; sy += v3.y; sz += v3.z; }
            exy[i] = make_float2(sx, sy);
            ez[i]  = sz;
        }
    }
    __syncthreads();

    int row = b * NN + rt * 256 + t;

    const uint4* gw = (const uint4*)(g_bits + (size_t)row * WROW + s * 8);
    uint4 w0 = gw[0], w1 = gw[1];
    unsigned words[8] = { w0.x, w0.y, w0.z, w0.w, w1.x, w1.y, w1.z, w1.w };

    unsigned bxy = (unsigned)__cvta_generic_to_shared(sxy);
    unsigned bz  = (unsigned)__cvta_generic_to_shared(szl);

    ull  accxy0 = 0ull, accxy1 = 0ull;
    float accz0 = 0.f,  accz1 = 0.f;

#pragma unroll
    for (int wl = 0; wl < 8; ++wl) {
        unsigned w = words[wl];
        unsigned rxy = bxy + wl * 1024;   // 8 quads * 128B
        unsigned rz  = bz  + wl * 512;    // 8 quads * 64B
#pragma unroll
        for (int k = 0; k < 8; k += 2) {
            unsigned idx0 = (w >> (4 * k)) & 15u;
            unsigned idx1 = (w >> (4 * k + 4)) & 15u;
            unsigned axy0 = rxy + k * 128 + idx0 * 8;
            unsigned axy1 = rxy + k * 128 + 128 + idx1 * 8;
            unsigned az0  = rz  + k * 64 + idx0 * 4;
            unsigned az1  = rz  + k * 64 + 64 + idx1 * 4;
            ull vxy0, vxy1;
            float vz0, vz1;
            asm volatile("ld.shared.b64 %0, [%1];" : "=l"(vxy0) : "r"(axy0));
            asm volatile("ld.shared.b64 %0, [%1];" : "=l"(vxy1) : "r"(axy1));
            asm volatile("ld.shared.f32 %0, [%1];" : "=f"(vz0) : "r"(az0));
            asm volatile("ld.shared.f32 %0, [%1];" : "=f"(vz1) : "r"(az1));
            asm volatile("add.rn.f32x2 %0, %0, %1;" : "+l"(accxy0) : "l"(vxy0));
            asm volatile("add.rn.f32x2 %0, %0, %1;" : "+l"(accxy1) : "l"(vxy1));
            accz0 += vz0;
            accz1 += vz1;
        }
    }

    ull accxy;
    asm volatile("add.rn.f32x2 %0, %1, %2;" : "=l"(accxy) : "l"(accxy0), "l"(accxy1));
    float ax, ay;
    asm volatile("mov.b64 {%0, %1}, %2;" : "=f"(ax), "=f"(ay) : "l"(accxy));
    part[s * ROWS + row] = make_float4(ax, ay, accz0 + accz1, 0.f);
}

// ---------------- agg layer 1 + fused v2 epilogue (last-arriving block) --------
__global__ void __launch_bounds__(256) agg1_kernel(
    const float* __restrict__ W2, const float* __restrict__ b1)
{
    int bx = blockIdx.x;
    int b  = bx >> 8;
    int rt = (bx >> 4) & 15;
    int s  = bx & 15;
    int t  = threadIdx.x;

    agg_core(g_v, g_pa, b, rt, s, t);

    __shared__ unsigned s_last;
    __threadfence();
    __syncthreads();
    if (t == 0) s_last = atomicAdd(&g_ctr0[b * 16 + rt], 1u);
    __syncthreads();
    if (s_last == 15u) {
        __threadfence();
        int id = b * NN + rt * 256 + t;
        float sx = 0.f, sy = 0.f, sz = 0.f;
#pragma unroll
        for (int qq = 0; qq < NQ; ++qq) {
            float4 p = __ldcg(&g_pa[qq * ROWS + id]);
            sx += p.x; sy += p.y; sz += p.z;
        }
        float d = g_dinv[id];
        float h0 = fmaxf(d * sx + b1[0], 0.f);
        float h1 = fmaxf(d * sy + b1[1], 0.f);
        float h2 = fmaxf(d * sz + b1[2], 0.f);
        float u0 = h0*W2[0] + h1*W2[3] + h2*W2[6];
        float u1 = h0*W2[1] + h1*W2[4] + h2*W2[7];
        float u2 = h0*W2[2] + h1*W2[5] + h2*W2[8];
        g_v2[id] = make_float4(d*u0, d*u1, d*u2, 0.f);
    }
}

// ---------------- agg layer 2 + fused combine2 epilogue ----------------
__global__ void __launch_bounds__(256) agg2_kernel(const float* __restrict__ b2)
{
    int bx = blockIdx.x;
    int b  = bx >> 8;
    int rt = (bx >> 4) & 15;
    int s  = bx & 15;
    int t  = threadIdx.x;

    agg_core(g_v2, g_pb, b, rt, s, t);

    __shared__ unsigned s_last;
    __threadfence();
    __syncthreads();
    if (t == 0) s_last = atomicAdd(&g_ctr1[b * 16 + rt], 1u);
    __syncthreads();
    if (s_last == 15u) {
        __threadfence();
        int id = b * NN + rt * 256 + t;
        float sx = 0.f, sy = 0.f, sz = 0.f;
#pragma unroll
        for (int qq = 0; qq < NQ; ++qq) {
            float4 p = __ldcg(&g_pb[qq * ROWS + id]);
            sx += p.x; sy += p.y; sz += p.z;
        }
        float d = g_dinv[id];
        g_h2[id] = make_float4(d * sx + b2[0], d * sy + b2[1], d * sz + b2[2], 0.f);
    }
}

// ---------------- fc1 split-K, coalesced row-major weight read ------------------
// Block = 4 warps. Warp w handles rows k0+w, k0+w+4, ... Lane l owns output
// columns 4l..4l+3: per row one fully-coalesced 512B warp load of fcW1.
__global__ void __launch_bounds__(128) fc1_kernel(
    const float* __restrict__ idxin, const float* __restrict__ y,
    const float* __restrict__ fcW1, const float* __restrict__ fcW2,
    const float* __restrict__ fcb2, float* __restrict__ out)
{
    __shared__ float  zc[CK];
    __shared__ float4 sred[4 * 32];   // 16B-aligned cross-warp reduction buffer
    int bx = blockIdx.x;
    int b  = bx >> 7;            // batch
    int s  = bx & 127;           // split
    int k0 = s * CK;
    int klen = min(CK, INDIM - k0);
    int t = threadIdx.x;
    int warp = t >> 5, lane = t & 31;

    for (int kk = t; kk < klen; kk += 128) {
        int k = k0 + kk;
        float z;
        if (k < NN) {
            z = idxin[b * NN + k];
        } else if (k < NN + 3 * NN) {
            int g = k - NN;
            int i = g / 3;
            int f = g - i * 3;
            z = ((const float*)&g_h2[b * NN + i])[f];
        } else {
            z = y[b * 36 + (k - (NN + 3 * NN))];
        }
        zc[kk] = z;
    }
    __syncthreads();

    const float4* W4 = (const float4*)fcW1;   // row k = W4[k*32 + lane]
    float ax = 0.f, ay = 0.f, az = 0.f, aw = 0.f;

    int kk = warp;
    for (; kk + 12 < klen; kk += 16) {
        float4 w0 = W4[(size_t)(k0 + kk)      * 32 + lane];
        float4 w1 = W4[(size_t)(k0 + kk + 4)  * 32 + lane];
        float4 w2 = W4[(size_t)(k0 + kk + 8)  * 32 + lane];
        float4 w3 = W4[(size_t)(k0 + kk + 12) * 32 + lane];
        float z0 = zc[kk], z1 = zc[kk + 4], z2 = zc[kk + 8], z3 = zc[kk + 12];
        ax += z0 * w0.x; ay += z0 * w0.y; az += z0 * w0.z; aw += z0 * w0.w;
        ax += z1 * w1.x; ay += z1 * w1.y; az += z1 * w1.z; aw += z1 * w1.w;
        ax += z2 * w2.x; ay += z2 * w2.y; az += z2 * w2.z; aw += z2 * w2.w;
        ax += z3 * w3.x; ay += z3 * w3.y; az += z3 * w3.z; aw += z3 * w3.w;
    }
    for (; kk < klen; kk += 4) {
        float4 w0 = W4[(size_t)(k0 + kk) * 32 + lane];
        float z0 = zc[kk];
        ax += z0 * w0.x; ay += z0 * w0.y; az += z0 * w0.z; aw += z0 * w0.w;
    }

    // cross-warp reduce in smem, then 128 atomics (one per column)
    sred[warp * 32 + lane] = make_float4(ax, ay, az, aw);
    __syncthreads();
    {
        const float* sr = (const float*)sred;
        float v = sr[t] + sr[HID + t] + sr[2 * HID + t] + sr[3 * HID + t];
        atomicAdd(&g_zacc[b * HID + t], v);
    }

    // last of the BB*FCSPLIT blocks computes fc2 (128 = 8 batches x 16 actions)
    __shared__ unsigned s_last;
    __threadfence();
    __syncthreads();
    if (t == 0) s_last = atomicAdd(&g_fcc, 1u);
    __syncthreads();
    if (s_last == (unsigned)(BB * FCSPLIT - 1)) {
        __threadfence();
        int ob = t >> 4;          // batch
        int oa = t & 15;          // action
        float o = fcb2[oa];
#pragma unroll 8
        for (int h = 0; h < HID; ++h)
            o += fmaxf(__ldcg(&g_zacc[ob * HID + h]), 0.f) * fcW2[h * NACT + oa];
        out[ob * NACT + oa] = o;
    }
}

// ---------------- launch ----------------
extern "C" void kernel_launch(void* const* d_in, const int* in_sizes, int n_in,
                              void* d_out, int out_size)
{
    const float* idxin = (const float*)d_in[0];   // [8,4096]
    const float* x     = (const float*)d_in[1];   // [8,4096,3]
    const float* y     = (const float*)d_in[2];   // [8,12,3]
    const int*   adj   = (const int*)  d_in[3];   // [8,4096,4096]
    const float* W1    = (const float*)d_in[4];
    const float* b1    = (const float*)d_in[5];
    const float* W2    = (const float*)d_in[6];
    const float* b2    = (const float*)d_in[7];
    const float* fcW1  = (const float*)d_in[8];
    const float* fcb1  = (const float*)d_in[9];
    const float* fcW2  = (const float*)d_in[10];
    const float* fcb2  = (const float*)d_in[11];
    float* out = (float*)d_out;

    prep_kernel<<<ROWS / 8, 256>>>(adj, x, W1, fcb1);
    agg1_kernel<<<2048, 256>>>(W2, b1);
    agg2_kernel<<<2048, 256>>>(b2);
    fc1_kernel<<<BB * FCSPLIT, 128>>>(idxin, y, fcW1, fcW2, fcb2, out);
}